// round 8
// baseline (speedup 1.0000x reference)
#include <cuda_runtime.h>
#include <cuda_bf16.h>
#include <cstdint>
#include <cstddef>

#define TT  512
#define BSZ 64
#define IND 1024
#define HD  256
#define G3  768   // 3*HD

// ---------------- scratch (static __device__ — no allocations allowed) ----------------
__device__ float g_gx[(size_t)2 * TT * BSZ * G3];  // pre-activations per direction (bih folded in)
__device__ float g_ys[(size_t)2 * TT * BSZ * HD];  // per-step hidden outputs per direction

__device__ __align__(16) __nv_bfloat16 g_src_hi[(size_t)TT * BSZ * IND];
__device__ __align__(16) __nv_bfloat16 g_src_lo[(size_t)TT * BSZ * IND];
__device__ __align__(16) __nv_bfloat16 g_wih_hi[(size_t)2 * G3 * IND];
__device__ __align__(16) __nv_bfloat16 g_wih_lo[(size_t)2 * G3 * IND];

// Whh pre-packed for streaming: [d][kc(16)][row(768)][16 bf16], hi and lo
__device__ __align__(16) __nv_bfloat16 g_whh_his[(size_t)2 * 16 * G3 * 16];
__device__ __align__(16) __nv_bfloat16 g_whh_los[(size_t)2 * 16 * G3 * 16];

// ---------------- helpers ----------------
__device__ __forceinline__ uint32_t smem_u32(const void* p) {
    uint32_t a;
    asm("{ .reg .u64 t; cvta.to.shared.u64 t, %1; cvt.u32.u64 %0, t; }" : "=r"(a) : "l"(p));
    return a;
}

#define CP16(dst, src) \
    asm volatile("cp.async.cg.shared.global [%0], [%1], 16;" :: "r"(dst), "l"(src))
#define CP_COMMIT() asm volatile("cp.async.commit_group;" ::: "memory")
#define CP_WAIT(n)  asm volatile("cp.async.wait_group %0;" :: "n"(n) : "memory")

#define LDSM4(R, addr) \
    asm volatile("ldmatrix.sync.aligned.m8n8.x4.shared.b16 {%0,%1,%2,%3}, [%4];" \
                 : "=r"((R)[0]), "=r"((R)[1]), "=r"((R)[2]), "=r"((R)[3]) : "r"(addr))

#define MMA16816(C, A, B0, B1) \
    asm volatile("mma.sync.aligned.m16n8k16.row.col.f32.bf16.bf16.f32 " \
                 "{%0,%1,%2,%3}, {%4,%5,%6,%7}, {%8,%9}, {%0,%1,%2,%3};" \
                 : "+f"((C)[0]), "+f"((C)[1]), "+f"((C)[2]), "+f"((C)[3]) \
                 : "r"((A)[0]), "r"((A)[1]), "r"((A)[2]), "r"((A)[3]), "r"(B0), "r"(B1))

// ---------------- f32x2 packed helpers ----------------
__device__ __forceinline__ unsigned long long pk2(float x, float y) {
    unsigned long long r;
    asm("mov.b64 %0, {%1, %2};" : "=l"(r) : "f"(x), "f"(y));
    return r;
}
__device__ __forceinline__ void upk2(unsigned long long v, float& x, float& y) {
    asm("mov.b64 {%0, %1}, %2;" : "=f"(x), "=f"(y) : "l"(v));
}
__device__ __forceinline__ void ffma2(unsigned long long& d, unsigned long long a, unsigned long long b) {
    asm("fma.rn.f32x2 %0, %1, %2, %0;" : "+l"(d) : "l"(a), "l"(b));
}

// =====================================================================
// Kernel 0: split fp32 -> (hi, lo) bf16 pair. which: 0=src, 1=Wih_f, 2=Wih_b
// =====================================================================
__global__ void __launch_bounds__(256) split_bf16(const float* __restrict__ x, int which, int n)
{
    __nv_bfloat16* hi;
    __nv_bfloat16* lo;
    if (which == 0)      { hi = g_src_hi;                    lo = g_src_lo; }
    else if (which == 1) { hi = g_wih_hi;                    lo = g_wih_lo; }
    else                 { hi = g_wih_hi + (size_t)G3 * IND; lo = g_wih_lo + (size_t)G3 * IND; }

    int i = (blockIdx.x * 256 + threadIdx.x) * 4;
    if (i >= n) return;
    float4 v = *(const float4*)(x + i);
    __nv_bfloat16 h0 = __float2bfloat16_rn(v.x);
    __nv_bfloat16 h1 = __float2bfloat16_rn(v.y);
    __nv_bfloat16 h2 = __float2bfloat16_rn(v.z);
    __nv_bfloat16 h3 = __float2bfloat16_rn(v.w);
    __nv_bfloat16 l0 = __float2bfloat16_rn(v.x - __bfloat162float(h0));
    __nv_bfloat16 l1 = __float2bfloat16_rn(v.y - __bfloat162float(h1));
    __nv_bfloat16 l2 = __float2bfloat16_rn(v.z - __bfloat162float(h2));
    __nv_bfloat16 l3 = __float2bfloat16_rn(v.w - __bfloat162float(h3));
    *(__nv_bfloat162*)(hi + i)     = __nv_bfloat162(h0, h1);
    *(__nv_bfloat162*)(hi + i + 2) = __nv_bfloat162(h2, h3);
    *(__nv_bfloat162*)(lo + i)     = __nv_bfloat162(l0, l1);
    *(__nv_bfloat162*)(lo + i + 2) = __nv_bfloat162(l2, l3);
}

// =====================================================================
// Kernel 0b: pack Whh into [d][kc][row][16] bf16 hi/lo chunks
// =====================================================================
__global__ void __launch_bounds__(256) whh_pack(const float* __restrict__ Whh_f,
                                                const float* __restrict__ Whh_b)
{
    int t = blockIdx.x * 256 + threadIdx.x;   // (d, row, kc)
    if (t >= 2 * G3 * 16) return;
    int d   = t / (G3 * 16);
    int r2  = t - d * (G3 * 16);
    int row = r2 >> 4;
    int kc  = r2 & 15;
    const float* W = d ? Whh_b : Whh_f;
    const float* src = W + (size_t)row * HD + kc * 16;
    size_t o = (((size_t)d * 16 + kc) * G3 + row) * 16;
#pragma unroll
    for (int kk = 0; kk < 16; kk++) {
        float v = src[kk];
        __nv_bfloat16 h = __float2bfloat16_rn(v);
        g_whh_his[o + kk] = h;
        g_whh_los[o + kk] = __float2bfloat16_rn(v - __bfloat162float(h));
    }
}

// =====================================================================
// Kernel A: gx via mma.sync (HMMA) bf16 split 3-MMA. (unchanged, R6)
// =====================================================================
#define GX_ROWB      80
#define GX_MAT       (128 * GX_ROWB)
#define GX_OFF_A_HI  0
#define GX_OFF_A_LO  (GX_MAT)
#define GX_OFF_B_HI  (2 * GX_MAT)
#define GX_OFF_B_LO  (3 * GX_MAT)
#define GX_STAGE     (4 * GX_MAT)
#define GX_SMEM_TOTAL (2 * GX_STAGE)

__global__ void __launch_bounds__(512) gx_mma(const float* __restrict__ bih_f,
                                              const float* __restrict__ bih_b)
{
    extern __shared__ char smem[];
    const uint32_t sbase = smem_u32(smem);
    const int tid = threadIdx.x;
    const int wid = tid >> 5;
    const int lid = tid & 31;
    const int wm  = wid >> 2;
    const int wn  = wid & 3;

    const int n0 = blockIdx.x * 128;
    const int m0 = blockIdx.y * 128;
    const int d  = blockIdx.z;

    const __nv_bfloat16* __restrict__ whi = g_wih_hi + (size_t)d * G3 * IND;
    const __nv_bfloat16* __restrict__ wlo = g_wih_lo + (size_t)d * G3 * IND;
    const float* __restrict__ bih = d ? bih_b : bih_f;

    const int rowL = tid & 127;
    const int sub  = tid >> 7;
    int mA = m0 + rowL;
    int srow = d ? ((TT - 1 - (mA >> 6)) * BSZ + (mA & 63)) : mA;
    const __nv_bfloat16* gA_hi = g_src_hi + (size_t)srow * IND + sub * 8;
    const __nv_bfloat16* gA_lo = g_src_lo + (size_t)srow * IND + sub * 8;
    const __nv_bfloat16* gB_hi = whi + (size_t)(n0 + rowL) * IND + sub * 8;
    const __nv_bfloat16* gB_lo = wlo + (size_t)(n0 + rowL) * IND + sub * 8;
    const uint32_t soLoad = (uint32_t)(rowL * GX_ROWB + sub * 16);

    const int blk = lid >> 3, rr = lid & 7;
    const uint32_t aoff = (uint32_t)(((wm * 32 + (blk & 1) * 8 + rr) * 40 + (blk >> 1) * 8) * 2);
    const uint32_t boff = (uint32_t)(((wn * 32 + (blk & 1) * 8 + rr) * 40 + (blk >> 1) * 8) * 2);

    float acc[2][4][4];
#pragma unroll
    for (int i = 0; i < 2; i++)
#pragma unroll
        for (int j = 0; j < 4; j++)
#pragma unroll
            for (int q = 0; q < 4; q++) acc[i][j][q] = 0.f;

    auto load_chunk = [&](int kc, int stage) {
        const int kb = kc * 32;
        const uint32_t s0 = sbase + stage * GX_STAGE;
        CP16(s0 + GX_OFF_A_HI + soLoad, gA_hi + kb);
        CP16(s0 + GX_OFF_A_LO + soLoad, gA_lo + kb);
        CP16(s0 + GX_OFF_B_HI + soLoad, gB_hi + kb);
        CP16(s0 + GX_OFF_B_LO + soLoad, gB_lo + kb);
        CP_COMMIT();
    };

    load_chunk(0, 0);

    for (int kc = 0; kc < 32; kc++) {
        const int cur = kc & 1;
        if (kc < 31) load_chunk(kc + 1, cur ^ 1);
        if (kc < 31) { CP_WAIT(1); } else { CP_WAIT(0); }
        __syncthreads();

        const uint32_t s0 = sbase + cur * GX_STAGE;
#pragma unroll
        for (int ks = 0; ks < 2; ks++) {
            const uint32_t koff = ks * 32;
            uint32_t ah[2][4], al[2][4];
            LDSM4(ah[0], s0 + GX_OFF_A_HI + aoff + koff);
            LDSM4(ah[1], s0 + GX_OFF_A_HI + aoff + 16 * GX_ROWB + koff);
            LDSM4(al[0], s0 + GX_OFF_A_LO + aoff + koff);
            LDSM4(al[1], s0 + GX_OFF_A_LO + aoff + 16 * GX_ROWB + koff);
            uint32_t bh[2][4], bl[2][4];
#pragma unroll
            for (int p = 0; p < 2; p++) {
                LDSM4(bh[p], s0 + GX_OFF_B_HI + boff + p * 16 * GX_ROWB + koff);
                LDSM4(bl[p], s0 + GX_OFF_B_LO + boff + p * 16 * GX_ROWB + koff);
            }
#pragma unroll
            for (int tm = 0; tm < 2; tm++) {
#pragma unroll
                for (int tn = 0; tn < 4; tn++) {
                    const int p = tn >> 1, o = tn & 1;
                    MMA16816(acc[tm][tn], ah[tm], bh[p][o], bh[p][2 + o]);
                    MMA16816(acc[tm][tn], ah[tm], bl[p][o], bl[p][2 + o]);
                    MMA16816(acc[tm][tn], al[tm], bh[p][o], bh[p][2 + o]);
                }
            }
        }
        __syncthreads();
    }

    const int g  = lid >> 2;
    const int t4 = lid & 3;
    const size_t dbase = (size_t)d * TT * BSZ;
#pragma unroll
    for (int tm = 0; tm < 2; tm++) {
        int mr = m0 + wm * 32 + tm * 16 + g;
#pragma unroll
        for (int tn = 0; tn < 4; tn++) {
            int col = n0 + wn * 32 + tn * 8 + t4 * 2;
            float2 bv = *(const float2*)(bih + col);
            float2 v0 = make_float2(acc[tm][tn][0] + bv.x, acc[tm][tn][1] + bv.y);
            float2 v1 = make_float2(acc[tm][tn][2] + bv.x, acc[tm][tn][3] + bv.y);
            *(float2*)(g_gx + (dbase + mr) * G3 + col)     = v0;
            *(float2*)(g_gx + (dbase + mr + 8) * G3 + col) = v1;
        }
    }
}

// =====================================================================
// Kernel B (NEW): GRU recurrence. 8 CTAs = (2 dir) x (4 batch-groups of 16).
// No clusters, no DSMEM, no grid sync. Per step:
//   gh[16x768] = h[16x256] @ WhhT via HMMA 3-split, Whh streamed from L2
//   into per-warp private double-buffered SMEM (per-warp cp.async groups,
//   NO syncthreads in the K loop). h lives in registers (thread owns
//   (batch=wid, units lid*8..+7)); hi/lo bf16 copies of h in SMEM for A-frags.
// =====================================================================
#define GRU_WBUF   0
#define GRU_WARPB  9216                   // 2 stages x (hi 2304 + lo 2304)
#define GRU_HHI    (16 * GRU_WARPB)       // 147456
#define GRU_HLO    (GRU_HHI + 8448)
#define GRU_SMEM   (GRU_HLO + 8448)       // 164352
#define GH_PITCH   776                    // floats per gh row

__global__ void __launch_bounds__(512, 1) gru_rec(
    const float* __restrict__ bhh_f, const float* __restrict__ bhh_b)
{
    extern __shared__ char smem[];
    const uint32_t sbase = smem_u32(smem);
    const int tid = threadIdx.x;
    const int wid = tid >> 5;
    const int lid = tid & 31;

    const int d  = blockIdx.x >> 2;
    const int bg = blockIdx.x & 3;
    const int B0 = bg * 16;

    const float* __restrict__ bhh = d ? bhh_b : bhh_f;

    // update-phase ownership: batch = wid (0..15), units j0..j0+7
    const int b  = wid;
    const int j0 = lid * 8;

    // biases (registers, loaded once)
    float br[8], bz[8], bn[8];
    *(float4*)(br)     = *(const float4*)(bhh + j0);
    *(float4*)(br + 4) = *(const float4*)(bhh + j0 + 4);
    *(float4*)(bz)     = *(const float4*)(bhh + HD + j0);
    *(float4*)(bz + 4) = *(const float4*)(bhh + HD + j0 + 4);
    *(float4*)(bn)     = *(const float4*)(bhh + 2 * HD + j0);
    *(float4*)(bn + 4) = *(const float4*)(bhh + 2 * HD + j0 + 4);

    float hreg[8];
#pragma unroll
    for (int u = 0; u < 8; u++) hreg[u] = 0.f;

    // zero h_hi / h_lo (includes padding)
    for (int i = tid; i < 2112; i += 512) {
        *(uint32_t*)(smem + GRU_HHI + i * 4) = 0u;
        *(uint32_t*)(smem + GRU_HLO + i * 4) = 0u;
    }
    __syncthreads();

    // ldmatrix lane offsets
    const int blk = lid >> 3, rr = lid & 7;
    const uint32_t arow  = (uint32_t)(((blk & 1) * 8 + rr) * 528 + (blk >> 1) * 16);
    const uint32_t aHI   = sbase + GRU_HHI + arow;
    const uint32_t aLO   = sbase + GRU_HLO + arow;
    const uint32_t bloff = (uint32_t)(((blk & 1) * 8 + rr) * 48 + (blk >> 1) * 16);
    const uint32_t wb    = sbase + GRU_WBUF + wid * GRU_WARPB;

    // per-warp Whh source rows [wid*48, wid*48+48)
    const size_t wsrc_base = ((size_t)d * 16 * G3 + (size_t)wid * 48) * 16;

    auto cpW = [&](int kc, int st) {
        const char* sH = (const char*)(g_whh_his + wsrc_base + (size_t)kc * G3 * 16);
        const char* sL = (const char*)(g_whh_los + wsrc_base + (size_t)kc * G3 * 16);
        uint32_t db = wb + st * 4608;
#pragma unroll
        for (int i = 0; i < 3; i++) {
            int seg = lid + 32 * i;          // 0..95
            int row = seg >> 1, half = seg & 1;
            uint32_t doff = (uint32_t)(row * 48 + half * 16);
            uint32_t soff = (uint32_t)(row * 32 + half * 16);
            CP16(db + doff, sH + soff);
            CP16(db + 2304 + doff, sL + soff);
        }
        CP_COMMIT();
    };

    for (int t = 0; t < TT; ++t) {
        // prefetch gx (consumed ~2500 cyc later in update phase)
        const size_t gxb = ((size_t)d * TT * BSZ + (size_t)t * BSZ + (B0 + b)) * G3 + j0;
        float4 gr0 = *(const float4*)(g_gx + gxb);
        float4 gr1 = *(const float4*)(g_gx + gxb + 4);
        float4 gz0 = *(const float4*)(g_gx + gxb + HD);
        float4 gz1 = *(const float4*)(g_gx + gxb + HD + 4);
        float4 gn0 = *(const float4*)(g_gx + gxb + 2 * HD);
        float4 gn1 = *(const float4*)(g_gx + gxb + 2 * HD + 4);

        float acc[3][2][4];
#pragma unroll
        for (int p = 0; p < 3; p++)
#pragma unroll
            for (int o = 0; o < 2; o++)
#pragma unroll
                for (int q = 0; q < 4; q++) acc[p][o][q] = 0.f;

        cpW(0, 0);
#pragma unroll 2
        for (int kc = 0; kc < 16; kc++) {
            if (kc < 15) cpW(kc + 1, (kc + 1) & 1);
            if (kc < 15) { CP_WAIT(1); } else { CP_WAIT(0); }
            const uint32_t db = wb + (kc & 1) * 4608;
            uint32_t ahi[4], alo[4];
            LDSM4(ahi, aHI + kc * 32);
            LDSM4(alo, aLO + kc * 32);
#pragma unroll
            for (int p = 0; p < 3; p++) {
                uint32_t bh[4], bl[4];
                LDSM4(bh, db + p * (16 * 48) + bloff);
                LDSM4(bl, db + 2304 + p * (16 * 48) + bloff);
#pragma unroll
                for (int o = 0; o < 2; o++) {
                    MMA16816(acc[p][o], ahi, bh[o], bh[2 + o]);
                    MMA16816(acc[p][o], ahi, bl[o], bl[2 + o]);
                    MMA16816(acc[p][o], alo, bh[o], bh[2 + o]);
                }
            }
        }
        __syncthreads();   // all warps done with WBUF; reuse as gh_sm

        // write gh fragments: rows = batches, cols = gate-units
        {
            const int row = lid >> 2;
            const int cb  = wid * 48 + (lid & 3) * 2;
#pragma unroll
            for (int p = 0; p < 3; p++)
#pragma unroll
                for (int o = 0; o < 2; o++) {
                    const int col = cb + p * 16 + o * 8;
                    *(float2*)(smem + ((size_t)row * GH_PITCH + col) * 4) =
                        make_float2(acc[p][o][0], acc[p][o][1]);
                    *(float2*)(smem + ((size_t)(row + 8) * GH_PITCH + col) * 4) =
                        make_float2(acc[p][o][2], acc[p][o][3]);
                }
        }
        __syncthreads();

        // update phase: thread owns (batch=b, units j0..j0+7)
        float ghr[8], ghz[8], ghn[8];
        *(float4*)(ghr)     = *(const float4*)(smem + ((size_t)b * GH_PITCH + j0) * 4);
        *(float4*)(ghr + 4) = *(const float4*)(smem + ((size_t)b * GH_PITCH + j0 + 4) * 4);
        *(float4*)(ghz)     = *(const float4*)(smem + ((size_t)b * GH_PITCH + HD + j0) * 4);
        *(float4*)(ghz + 4) = *(const float4*)(smem + ((size_t)b * GH_PITCH + HD + j0 + 4) * 4);
        *(float4*)(ghn)     = *(const float4*)(smem + ((size_t)b * GH_PITCH + 2 * HD + j0) * 4);
        *(float4*)(ghn + 4) = *(const float4*)(smem + ((size_t)b * GH_PITCH + 2 * HD + j0 + 4) * 4);

        float gxr[8], gxz[8], gxn[8];
        *(float4*)(gxr) = gr0; *(float4*)(gxr + 4) = gr1;
        *(float4*)(gxz) = gz0; *(float4*)(gxz + 4) = gz1;
        *(float4*)(gxn) = gn0; *(float4*)(gxn + 4) = gn1;

        float hnew[8];
#pragma unroll
        for (int u = 0; u < 8; u++) {
            float xr = gxr[u] + ghr[u] + br[u];
            float xz = gxz[u] + ghz[u] + bz[u];
            float r  = __fdividef(1.f, 1.f + __expf(-xr));
            float z  = __fdividef(1.f, 1.f + __expf(-xz));
            float a  = gxn[u] + r * (ghn[u] + bn[u]);
            float n  = 1.f - __fdividef(2.f, __expf(2.f * a) + 1.f);
            hnew[u]  = n + z * (hreg[u] - n);
            hreg[u]  = hnew[u];
        }

        // write outputs
        const size_t ysb = ((size_t)d * TT * BSZ + (size_t)t * BSZ + (B0 + b)) * HD + j0;
        *(float4*)(g_ys + ysb)     = *(float4*)(hnew);
        *(float4*)(g_ys + ysb + 4) = *(float4*)(hnew + 4);

        // republish h hi/lo bf16 into SMEM for next step's A-frags
        {
            __nv_bfloat162 ph[4], pl[4];
#pragma unroll
            for (int q = 0; q < 4; q++) {
                float x = hnew[2 * q], y = hnew[2 * q + 1];
                __nv_bfloat16 hx = __float2bfloat16_rn(x);
                __nv_bfloat16 hy = __float2bfloat16_rn(y);
                ph[q] = __nv_bfloat162(hx, hy);
                pl[q] = __nv_bfloat162(__float2bfloat16_rn(x - __bfloat162float(hx)),
                                       __float2bfloat16_rn(y - __bfloat162float(hy)));
            }
            *(uint4*)(smem + GRU_HHI + b * 528 + j0 * 2) = *(uint4*)(ph);
            *(uint4*)(smem + GRU_HLO + b * 528 + j0 * 2) = *(uint4*)(pl);
        }
        __syncthreads();
    }
}

// =====================================================================
// Kernel C: outputs GEMM (fp32 FFMA2, unchanged)
// =====================================================================
__global__ void __launch_bounds__(256) out_gemm(
    const float* __restrict__ Wout, const float* __restrict__ bout,
    float* __restrict__ out)
{
    const int m0 = blockIdx.x * 128;
    const int n0 = blockIdx.y * 64;

    __shared__ float As[16][132];
    __shared__ float Bs[16][68];

    const int tid = threadIdx.x;
    const int tx = tid & 7;
    const int ty = tid >> 3;

    unsigned long long acc[4][4];
#pragma unroll
    for (int i = 0; i < 4; i++)
#pragma unroll
        for (int j = 0; j < 4; j++) acc[i][j] = 0ull;

    for (int kt = 0; kt < 2 * HD; kt += 16) {
#pragma unroll
        for (int i = 0; i < 2; i++) {
            int idx = tid + i * 256;
            int mi = idx >> 2, ki = (idx & 3) << 2;
            int m = m0 + mi;
            size_t aoff;
            if (kt < HD) {
                aoff = (size_t)m * HD + kt + ki;
            } else {
                int tt = m >> 6, bb = m & 63;
                aoff = (size_t)TT * BSZ * HD +
                       ((size_t)(TT - 1 - tt) * BSZ + bb) * HD + (kt + ki - HD);
            }
            float4 v = *(const float4*)(g_ys + aoff);
            As[ki + 0][mi] = v.x; As[ki + 1][mi] = v.y;
            As[ki + 2][mi] = v.z; As[ki + 3][mi] = v.w;
        }
        {
            int ni = tid >> 2, ki = (tid & 3) << 2;
            float4 wv = *(const float4*)(Wout + (size_t)(n0 + ni) * (2 * HD) + kt + ki);
            Bs[ki + 0][ni] = wv.x; Bs[ki + 1][ni] = wv.y;
            Bs[ki + 2][ni] = wv.z; Bs[ki + 3][ni] = wv.w;
        }
        __syncthreads();
#pragma unroll
        for (int k = 0; k < 16; k++) {
            float4 a0 = *(const float4*)&As[k][ty * 4];
            ulonglong2 b0 = *(const ulonglong2*)&Bs[k][tx * 8];
            ulonglong2 b1 = *(const ulonglong2*)&Bs[k][tx * 8 + 4];
            float a[4] = {a0.x, a0.y, a0.z, a0.w};
            unsigned long long bb2[4] = {b0.x, b0.y, b1.x, b1.y};
#pragma unroll
            for (int i = 0; i < 4; i++) {
                unsigned long long ad = pk2(a[i], a[i]);
#pragma unroll
                for (int j = 0; j < 4; j++) ffma2(acc[i][j], ad, bb2[j]);
            }
        }
        __syncthreads();
    }

#pragma unroll
    for (int i = 0; i < 4; i++) {
        int m = m0 + ty * 4 + i;
        float* op = out + (size_t)m * HD + n0 + tx * 8;
#pragma unroll
        for (int j = 0; j < 4; j++) {
            float x, y;
            upk2(acc[i][j], x, y);
            int n = n0 + tx * 8 + j * 2;
            float2 o = make_float2(x + bout[n], y + bout[n + 1]);
            *(float2*)(op + j * 2) = o;
        }
    }
}

// =====================================================================
// Kernel D: hidden projection (unchanged)
// =====================================================================
__global__ void __launch_bounds__(256) hid_kernel(
    const float* __restrict__ Whid, const float* __restrict__ bhid,
    float* __restrict__ hid)
{
    const int b = blockIdx.x;
    const int o = threadIdx.x;
    __shared__ float hc[2 * HD];
    for (int k = threadIdx.x; k < 2 * HD; k += 256) {
        hc[k] = (k < HD)
            ? g_ys[((size_t)(TT - 1) * BSZ + b) * HD + k]
            : g_ys[(size_t)TT * BSZ * HD + ((size_t)(TT - 1) * BSZ + b) * HD + (k - HD)];
    }
    __syncthreads();
    float acc = bhid[o];
    const float4* wp = (const float4*)(Whid + (size_t)o * (2 * HD));
    const float4* hp = (const float4*)hc;
#pragma unroll 4
    for (int q = 0; q < (2 * HD) / 4; q++) {
        float4 wv = wp[q], hv = hp[q];
        acc += wv.x * hv.x + wv.y * hv.y + wv.z * hv.z + wv.w * hv.w;
    }
    hid[(size_t)b * HD + o] = tanhf(acc);
}

// =====================================================================
extern "C" void kernel_launch(void* const* d_in, const int* in_sizes, int n_in,
                              void* d_out, int out_size)
{
    const float* src   = (const float*)d_in[0];
    const float* Wih_f = (const float*)d_in[1];
    const float* Whh_f = (const float*)d_in[2];
    const float* bih_f = (const float*)d_in[3];
    const float* bhh_f = (const float*)d_in[4];
    const float* Wih_b = (const float*)d_in[5];
    const float* Whh_b = (const float*)d_in[6];
    const float* bih_b = (const float*)d_in[7];
    const float* bhh_b = (const float*)d_in[8];
    const float* Wout  = (const float*)d_in[9];
    const float* bout  = (const float*)d_in[10];
    const float* Whid  = (const float*)d_in[11];
    const float* bhid  = (const float*)d_in[12];
    float* out = (float*)d_out;

    cudaFuncSetAttribute(gx_mma, cudaFuncAttributeMaxDynamicSharedMemorySize, GX_SMEM_TOTAL);
    cudaFuncSetAttribute(gru_rec, cudaFuncAttributeMaxDynamicSharedMemorySize, GRU_SMEM);

    {
        int n_src = TT * BSZ * IND;
        int n_w   = G3 * IND;
        split_bf16<<<(n_src / 4 + 255) / 256, 256>>>(src, 0, n_src);
        split_bf16<<<(n_w   / 4 + 255) / 256, 256>>>(Wih_f, 1, n_w);
        split_bf16<<<(n_w   / 4 + 255) / 256, 256>>>(Wih_b, 2, n_w);
        whh_pack<<<(2 * G3 * 16 + 255) / 256, 256>>>(Whh_f, Whh_b);
    }

    gx_mma<<<dim3(G3 / 128, TT * BSZ / 128, 2), 512, GX_SMEM_TOTAL>>>(bih_f, bih_b);
    gru_rec<<<8, 512, GRU_SMEM>>>(bhh_f, bhh_b);
    out_gemm<<<dim3(TT * BSZ / 128, HD / 64), 256>>>(Wout, bout, out);
    hid_kernel<<<BSZ, 256>>>(Whid, bhid, out + (size_t)TT * BSZ * HD);
}

// round 10
// speedup vs baseline: 3.0885x; 3.0885x over previous
#include <cuda_runtime.h>
#include <cuda_bf16.h>
#include <cstdint>
#include <cstddef>

#define TT  512
#define BSZ 64
#define IND 1024
#define HD  256
#define G3  768   // 3*HD

// ---------------- scratch (static __device__ — no allocations allowed) ----------------
__device__ float g_gx[(size_t)2 * TT * BSZ * G3];  // pre-activations per direction (bih folded in)
__device__ float g_ys[(size_t)2 * TT * BSZ * HD];  // per-step hidden outputs per direction

__device__ __align__(16) __nv_bfloat16 g_src_hi[(size_t)TT * BSZ * IND];
__device__ __align__(16) __nv_bfloat16 g_src_lo[(size_t)TT * BSZ * IND];
__device__ __align__(16) __nv_bfloat16 g_wih_hi[(size_t)2 * G3 * IND];
__device__ __align__(16) __nv_bfloat16 g_wih_lo[(size_t)2 * G3 * IND];

// Whh packed bf16 hi/lo, plain row-major: [d][plane][row 768][col 256]
__device__ __align__(16) __nv_bfloat16 g_whhp[(size_t)2 * 2 * G3 * HD];

// h exchange buffer: [d][parity][plane hi/lo][batch 64][unit 256] bf16
__device__ __align__(16) __nv_bfloat16 g_hx[(size_t)2 * 2 * 2 * BSZ * HD];

// per-direction step barrier counters
__device__ unsigned g_bar[2];

// ---------------- helpers ----------------
__device__ __forceinline__ uint32_t smem_u32(const void* p) {
    uint32_t a;
    asm("{ .reg .u64 t; cvta.to.shared.u64 t, %1; cvt.u32.u64 %0, t; }" : "=r"(a) : "l"(p));
    return a;
}

#define CP16(dst, src) \
    asm volatile("cp.async.cg.shared.global [%0], [%1], 16;" :: "r"(dst), "l"(src))
#define CP_COMMIT() asm volatile("cp.async.commit_group;" ::: "memory")
#define CP_WAIT(n)  asm volatile("cp.async.wait_group %0;" :: "n"(n) : "memory")

#define LDSM4(R, addr) \
    asm volatile("ldmatrix.sync.aligned.m8n8.x4.shared.b16 {%0,%1,%2,%3}, [%4];" \
                 : "=r"((R)[0]), "=r"((R)[1]), "=r"((R)[2]), "=r"((R)[3]) : "r"(addr))

#define MMA16816(C, A, B0, B1) \
    asm volatile("mma.sync.aligned.m16n8k16.row.col.f32.bf16.bf16.f32 " \
                 "{%0,%1,%2,%3}, {%4,%5,%6,%7}, {%8,%9}, {%0,%1,%2,%3};" \
                 : "+f"((C)[0]), "+f"((C)[1]), "+f"((C)[2]), "+f"((C)[3]) \
                 : "r"((A)[0]), "r"((A)[1]), "r"((A)[2]), "r"((A)[3]), "r"(B0), "r"(B1))

// ---------------- f32x2 packed helpers ----------------
__device__ __forceinline__ unsigned long long pk2(float x, float y) {
    unsigned long long r;
    asm("mov.b64 %0, {%1, %2};" : "=l"(r) : "f"(x), "f"(y));
    return r;
}
__device__ __forceinline__ void upk2(unsigned long long v, float& x, float& y) {
    asm("mov.b64 {%0, %1}, %2;" : "=f"(x), "=f"(y) : "l"(v));
}
__device__ __forceinline__ void ffma2(unsigned long long& d, unsigned long long a, unsigned long long b) {
    asm("fma.rn.f32x2 %0, %1, %2, %0;" : "+l"(d) : "l"(a), "l"(b));
}

// =====================================================================
// Kernel 0: split fp32 -> (hi, lo) bf16 pair. which: 0=src, 1=Wih_f, 2=Wih_b
// =====================================================================
__global__ void __launch_bounds__(256) split_bf16(const float* __restrict__ x, int which, int n)
{
    __nv_bfloat16* hi;
    __nv_bfloat16* lo;
    if (which == 0)      { hi = g_src_hi;                    lo = g_src_lo; }
    else if (which == 1) { hi = g_wih_hi;                    lo = g_wih_lo; }
    else                 { hi = g_wih_hi + (size_t)G3 * IND; lo = g_wih_lo + (size_t)G3 * IND; }

    int i = (blockIdx.x * 256 + threadIdx.x) * 4;
    if (i >= n) return;
    float4 v = *(const float4*)(x + i);
    __nv_bfloat16 h0 = __float2bfloat16_rn(v.x);
    __nv_bfloat16 h1 = __float2bfloat16_rn(v.y);
    __nv_bfloat16 h2 = __float2bfloat16_rn(v.z);
    __nv_bfloat16 h3 = __float2bfloat16_rn(v.w);
    __nv_bfloat16 l0 = __float2bfloat16_rn(v.x - __bfloat162float(h0));
    __nv_bfloat16 l1 = __float2bfloat16_rn(v.y - __bfloat162float(h1));
    __nv_bfloat16 l2 = __float2bfloat16_rn(v.z - __bfloat162float(h2));
    __nv_bfloat16 l3 = __float2bfloat16_rn(v.w - __bfloat162float(h3));
    *(__nv_bfloat162*)(hi + i)     = __nv_bfloat162(h0, h1);
    *(__nv_bfloat162*)(hi + i + 2) = __nv_bfloat162(h2, h3);
    *(__nv_bfloat162*)(lo + i)     = __nv_bfloat162(l0, l1);
    *(__nv_bfloat162*)(lo + i + 2) = __nv_bfloat162(l2, l3);
}

// =====================================================================
// Kernel 0b: pack Whh -> bf16 hi/lo planes [d][plane][768][256]; reset barrier
// =====================================================================
__global__ void __launch_bounds__(256) whh_pack(const float* __restrict__ Whh_f,
                                                const float* __restrict__ Whh_b)
{
    if (blockIdx.x == 0 && threadIdx.x == 0) { g_bar[0] = 0u; g_bar[1] = 0u; }
    int t = blockIdx.x * 256 + threadIdx.x;      // (d, row, 16-col chunk)
    if (t >= 2 * G3 * 16) return;
    int d   = t / (G3 * 16);
    int r2  = t - d * (G3 * 16);
    int row = r2 >> 4;
    int ch  = r2 & 15;
    const float* W = d ? Whh_b : Whh_f;
    const float* src = W + (size_t)row * HD + ch * 16;
    size_t ohi = (((size_t)d * 2 + 0) * G3 + row) * HD + ch * 16;
    size_t olo = (((size_t)d * 2 + 1) * G3 + row) * HD + ch * 16;
#pragma unroll
    for (int kk = 0; kk < 16; kk++) {
        float v = src[kk];
        __nv_bfloat16 h = __float2bfloat16_rn(v);
        g_whhp[ohi + kk] = h;
        g_whhp[olo + kk] = __float2bfloat16_rn(v - __bfloat162float(h));
    }
}

// =====================================================================
// Kernel A: gx via mma.sync (HMMA) bf16 split 3-MMA. (unchanged)
// =====================================================================
#define GX_ROWB      80
#define GX_MAT       (128 * GX_ROWB)
#define GX_OFF_A_HI  0
#define GX_OFF_A_LO  (GX_MAT)
#define GX_OFF_B_HI  (2 * GX_MAT)
#define GX_OFF_B_LO  (3 * GX_MAT)
#define GX_STAGE     (4 * GX_MAT)
#define GX_SMEM_TOTAL (2 * GX_STAGE)

__global__ void __launch_bounds__(512) gx_mma(const float* __restrict__ bih_f,
                                              const float* __restrict__ bih_b)
{
    extern __shared__ char smem[];
    const uint32_t sbase = smem_u32(smem);
    const int tid = threadIdx.x;
    const int wid = tid >> 5;
    const int lid = tid & 31;
    const int wm  = wid >> 2;
    const int wn  = wid & 3;

    const int n0 = blockIdx.x * 128;
    const int m0 = blockIdx.y * 128;
    const int d  = blockIdx.z;

    const __nv_bfloat16* __restrict__ whi = g_wih_hi + (size_t)d * G3 * IND;
    const __nv_bfloat16* __restrict__ wlo = g_wih_lo + (size_t)d * G3 * IND;
    const float* __restrict__ bih = d ? bih_b : bih_f;

    const int rowL = tid & 127;
    const int sub  = tid >> 7;
    int mA = m0 + rowL;
    int srow = d ? ((TT - 1 - (mA >> 6)) * BSZ + (mA & 63)) : mA;
    const __nv_bfloat16* gA_hi = g_src_hi + (size_t)srow * IND + sub * 8;
    const __nv_bfloat16* gA_lo = g_src_lo + (size_t)srow * IND + sub * 8;
    const __nv_bfloat16* gB_hi = whi + (size_t)(n0 + rowL) * IND + sub * 8;
    const __nv_bfloat16* gB_lo = wlo + (size_t)(n0 + rowL) * IND + sub * 8;
    const uint32_t soLoad = (uint32_t)(rowL * GX_ROWB + sub * 16);

    const int blk = lid >> 3, rr = lid & 7;
    const uint32_t aoff = (uint32_t)(((wm * 32 + (blk & 1) * 8 + rr) * 40 + (blk >> 1) * 8) * 2);
    const uint32_t boff = (uint32_t)(((wn * 32 + (blk & 1) * 8 + rr) * 40 + (blk >> 1) * 8) * 2);

    float acc[2][4][4];
#pragma unroll
    for (int i = 0; i < 2; i++)
#pragma unroll
        for (int j = 0; j < 4; j++)
#pragma unroll
            for (int q = 0; q < 4; q++) acc[i][j][q] = 0.f;

    auto load_chunk = [&](int kc, int stage) {
        const int kb = kc * 32;
        const uint32_t s0 = sbase + stage * GX_STAGE;
        CP16(s0 + GX_OFF_A_HI + soLoad, gA_hi + kb);
        CP16(s0 + GX_OFF_A_LO + soLoad, gA_lo + kb);
        CP16(s0 + GX_OFF_B_HI + soLoad, gB_hi + kb);
        CP16(s0 + GX_OFF_B_LO + soLoad, gB_lo + kb);
        CP_COMMIT();
    };

    load_chunk(0, 0);

    for (int kc = 0; kc < 32; kc++) {
        const int cur = kc & 1;
        if (kc < 31) load_chunk(kc + 1, cur ^ 1);
        if (kc < 31) { CP_WAIT(1); } else { CP_WAIT(0); }
        __syncthreads();

        const uint32_t s0 = sbase + cur * GX_STAGE;
#pragma unroll
        for (int ks = 0; ks < 2; ks++) {
            const uint32_t koff = ks * 32;
            uint32_t ah[2][4], al[2][4];
            LDSM4(ah[0], s0 + GX_OFF_A_HI + aoff + koff);
            LDSM4(ah[1], s0 + GX_OFF_A_HI + aoff + 16 * GX_ROWB + koff);
            LDSM4(al[0], s0 + GX_OFF_A_LO + aoff + koff);
            LDSM4(al[1], s0 + GX_OFF_A_LO + aoff + 16 * GX_ROWB + koff);
            uint32_t bh[2][4], bl[2][4];
#pragma unroll
            for (int p = 0; p < 2; p++) {
                LDSM4(bh[p], s0 + GX_OFF_B_HI + boff + p * 16 * GX_ROWB + koff);
                LDSM4(bl[p], s0 + GX_OFF_B_LO + boff + p * 16 * GX_ROWB + koff);
            }
#pragma unroll
            for (int tm = 0; tm < 2; tm++) {
#pragma unroll
                for (int tn = 0; tn < 4; tn++) {
                    const int p = tn >> 1, o = tn & 1;
                    MMA16816(acc[tm][tn], ah[tm], bh[p][o], bh[p][2 + o]);
                    MMA16816(acc[tm][tn], ah[tm], bl[p][o], bl[p][2 + o]);
                    MMA16816(acc[tm][tn], al[tm], bh[p][o], bh[p][2 + o]);
                }
            }
        }
        __syncthreads();
    }

    const int g  = lid >> 2;
    const int t4 = lid & 3;
    const size_t dbase = (size_t)d * TT * BSZ;
#pragma unroll
    for (int tm = 0; tm < 2; tm++) {
        int mr = m0 + wm * 32 + tm * 16 + g;
#pragma unroll
        for (int tn = 0; tn < 4; tn++) {
            int col = n0 + wn * 32 + tn * 8 + t4 * 2;
            float2 bv = *(const float2*)(bih + col);
            float2 v0 = make_float2(acc[tm][tn][0] + bv.x, acc[tm][tn][1] + bv.y);
            float2 v1 = make_float2(acc[tm][tn][2] + bv.x, acc[tm][tn][3] + bv.y);
            *(float2*)(g_gx + (dbase + mr) * G3 + col)     = v0;
            *(float2*)(g_gx + (dbase + mr + 8) * G3 + col) = v1;
        }
    }
}

// =====================================================================
// Kernel B (v3, fixed): GRU recurrence. 32 CTAs = 2 dir x 16 unit-groups.
// =====================================================================
#define GP        528                       // SMEM row pitch bytes (256 bf16 + 16B pad)
#define GRU_W_HI  0
#define GRU_W_LO  (48 * GP)                 // 25344
#define GRU_H_HI  (2 * 48 * GP)             // 50688
#define GRU_H_LO  (GRU_H_HI + 64 * GP)      // 84480
#define GRU_GH    (GRU_H_LO + 64 * GP)      // 118272
#define GHP       52                        // gh row pitch (floats)
#define GRU_SMEM  (GRU_GH + 64 * GHP * 4)   // 131584

__global__ void __launch_bounds__(384, 1) gru_rec(
    const float* __restrict__ bhh_f, const float* __restrict__ bhh_b)
{
    extern __shared__ char smem[];
    const uint32_t sbase = smem_u32(smem);
    const int tid = threadIdx.x;
    const int wid = tid >> 5;
    const int lid = tid & 31;
    const int wm  = wid & 3;        // m-tile: batches wm*16..+15
    const int wg  = wid >> 2;       // gate 0..2 (n-tile)

    const int d    = blockIdx.x >> 4;
    const int ctaG = blockIdx.x & 15;      // unit group: units ctaG*16..+15

    const float* __restrict__ bhh = d ? bhh_b : bhh_f;

    // ---- load Whh slice into SMEM (once) ----
    // 1536 = 48 rows x 32 segs per plane, 2 planes -> 3072 total
    for (int idx = tid; idx < 3072; idx += 384) {
        int plane = idx / 1536;              // 0 hi, 1 lo
        int rem   = idx - plane * 1536;
        int rloc  = rem >> 5;                // 0..47
        int seg   = rem & 31;                // 16B seg
        int grow  = (rloc >> 4) * HD + ctaG * 16 + (rloc & 15);
        const char* src = (const char*)(g_whhp +
            (((size_t)d * 2 + plane) * G3 + grow) * HD) + seg * 16;
        uint32_t dst = sbase + (plane ? GRU_W_LO : GRU_W_HI) + rloc * GP + seg * 16;
        CP16(dst, src);
    }
    CP_COMMIT();

    // ---- zero h SMEM planes ----
    for (int i = tid; i < (64 * GP) / 8; i += 384) {
        *(uint64_t*)(smem + GRU_H_HI + i * 8) = 0ull;
        *(uint64_t*)(smem + GRU_H_LO + i * 8) = 0ull;
    }
    CP_WAIT(0);
    __syncthreads();

    // ---- ldmatrix lane offsets ----
    const int blk = lid >> 3, rr = lid & 7;
    const uint32_t aAddr = sbase + GRU_H_HI + (uint32_t)((wm * 16 + (blk & 1) * 8 + rr) * GP + (blk >> 1) * 16);
    const uint32_t aAddrL = aAddr + (GRU_H_LO - GRU_H_HI);
    const uint32_t bAddr = sbase + GRU_W_HI + (uint32_t)((wg * 16 + (blk & 1) * 8 + rr) * GP + (blk >> 1) * 16);
    const uint32_t bAddrL = bAddr + (GRU_W_LO - GRU_W_HI);

    // ---- update-phase ownership (threads 0..255): batch b, 4 units j4..j4+3 ----
    const int ub  = tid >> 2;
    const int j4  = (tid & 3) * 4;
    const int gcol = ctaG * 16 + j4;       // global unit col
    float br4[4], bz4[4], bn4[4], hprev[4];
    if (tid < 256) {
        *(float4*)br4 = *(const float4*)(bhh + gcol);
        *(float4*)bz4 = *(const float4*)(bhh + HD + gcol);
        *(float4*)bn4 = *(const float4*)(bhh + 2 * HD + gcol);
    }
#pragma unroll
    for (int u = 0; u < 4; u++) hprev[u] = 0.f;

    const unsigned bar_target_step = 16u;
    for (int t = 0; t < TT; ++t) {
        // ---- prefetch gx for update phase ----
        float gxr[4], gxz[4], gxn[4];
        if (tid < 256) {
            const size_t mrow = (size_t)d * TT * BSZ + (size_t)t * BSZ + ub;
            *(float4*)gxr = *(const float4*)(g_gx + mrow * G3 + gcol);
            *(float4*)gxz = *(const float4*)(g_gx + mrow * G3 + HD + gcol);
            *(float4*)gxn = *(const float4*)(g_gx + mrow * G3 + 2 * HD + gcol);
        }

        // ---- pull h (written by all 16 CTAs at step t-1) ----
        if (t > 0) {
            const int par = (t - 1) & 1;
            const __nv_bfloat16* hb = g_hx + (((size_t)d * 2 + par) * 2) * BSZ * HD;
            for (int idx = tid; idx < 4096; idx += 384) {
                int plane = idx >> 11;           // 2048 = 64 rows x 32 segs per plane
                int rem   = idx & 2047;
                int row   = rem >> 5;            // batch
                int seg   = rem & 31;
                const char* src = (const char*)(hb + (size_t)plane * BSZ * HD + (size_t)row * HD) + seg * 16;
                uint32_t dst = sbase + (plane ? GRU_H_LO : GRU_H_HI) + row * GP + seg * 16;
                CP16(dst, src);
            }
            CP_COMMIT();
            CP_WAIT(0);
            __syncthreads();
        }

        // ---- gh = h @ Whh_slice^T (HMMA 3-split), warp tile m16 x n16 ----
        float acc[2][4];
#pragma unroll
        for (int o = 0; o < 2; o++)
#pragma unroll
            for (int q = 0; q < 4; q++) acc[o][q] = 0.f;

#pragma unroll
        for (int k = 0; k < 16; k++) {
            const uint32_t ko = k * 32;
            uint32_t ah[4], al[4], bh[4], bl[4];
            LDSM4(ah, aAddr + ko);
            LDSM4(al, aAddrL + ko);
            LDSM4(bh, bAddr + ko);
            LDSM4(bl, bAddrL + ko);
#pragma unroll
            for (int o = 0; o < 2; o++) {
                MMA16816(acc[o], ah, bh[o], bh[2 + o]);
                MMA16816(acc[o], ah, bl[o], bl[2 + o]);
                MMA16816(acc[o], al, bh[o], bh[2 + o]);
            }
        }

        // ---- stage gh to SMEM: [batch][gate*16 + unit] ----
        {
            const int row = wm * 16 + (lid >> 2);
            const int col = wg * 16 + (lid & 3) * 2;
            float* gsm = (float*)(smem + GRU_GH);
#pragma unroll
            for (int o = 0; o < 2; o++) {
                *(float2*)(gsm + (size_t)row * GHP + col + o * 8)       = make_float2(acc[o][0], acc[o][1]);
                *(float2*)(gsm + (size_t)(row + 8) * GHP + col + o * 8) = make_float2(acc[o][2], acc[o][3]);
            }
        }
        __syncthreads();

        // ---- gate math + publish h ----
        if (tid < 256) {
            const float* gsm = (const float*)(smem + GRU_GH) + (size_t)ub * GHP;
            float ghr[4], ghz[4], ghn[4];
            *(float4*)ghr = *(const float4*)(gsm + j4);
            *(float4*)ghz = *(const float4*)(gsm + 16 + j4);
            *(float4*)ghn = *(const float4*)(gsm + 32 + j4);

            float hnew[4];
#pragma unroll
            for (int u = 0; u < 4; u++) {
                float xr = gxr[u] + ghr[u] + br4[u];
                float xz = gxz[u] + ghz[u] + bz4[u];
                float r  = __fdividef(1.f, 1.f + __expf(-xr));
                float z  = __fdividef(1.f, 1.f + __expf(-xz));
                float a  = gxn[u] + r * (ghn[u] + bn4[u]);
                float n  = 1.f - __fdividef(2.f, __expf(2.f * a) + 1.f);
                hnew[u]  = n + z * (hprev[u] - n);
                hprev[u] = hnew[u];
            }

            // fp32 outputs
            const size_t mrow = (size_t)d * TT * BSZ + (size_t)t * BSZ + ub;
            *(float4*)(g_ys + mrow * HD + gcol) = *(float4*)hnew;

            // bf16 hi/lo h publish (8B each plane)
            const int par = t & 1;
            __nv_bfloat16* hb = g_hx + (((size_t)d * 2 + par) * 2) * BSZ * HD;
            __nv_bfloat162 ph[2], pl[2];
#pragma unroll
            for (int q = 0; q < 2; q++) {
                float x = hnew[2 * q], y = hnew[2 * q + 1];
                __nv_bfloat16 hx = __float2bfloat16_rn(x);
                __nv_bfloat16 hy = __float2bfloat16_rn(y);
                ph[q] = __nv_bfloat162(hx, hy);
                pl[q] = __nv_bfloat162(__float2bfloat16_rn(x - __bfloat162float(hx)),
                                       __float2bfloat16_rn(y - __bfloat162float(hy)));
            }
            *(uint2*)(hb + (size_t)ub * HD + gcol)                       = *(uint2*)ph;
            *(uint2*)(hb + (size_t)BSZ * HD + (size_t)ub * HD + gcol)    = *(uint2*)pl;
        }
        __threadfence();
        __syncthreads();

        // ---- per-direction barrier over 16 CTAs ----
        if (tid == 0) {
            atomicAdd(&g_bar[d], 1u);
            const unsigned target = bar_target_step * (unsigned)(t + 1);
            unsigned v;
            do {
                asm volatile("ld.acquire.gpu.global.u32 %0, [%1];" : "=r"(v) : "l"(g_bar + d));
            } while (v < target);
        }
        __syncthreads();
    }
}

// =====================================================================
// Kernel C: outputs GEMM (fp32 FFMA2, unchanged)
// =====================================================================
__global__ void __launch_bounds__(256) out_gemm(
    const float* __restrict__ Wout, const float* __restrict__ bout,
    float* __restrict__ out)
{
    const int m0 = blockIdx.x * 128;
    const int n0 = blockIdx.y * 64;

    __shared__ float As[16][132];
    __shared__ float Bs[16][68];

    const int tid = threadIdx.x;
    const int tx = tid & 7;
    const int ty = tid >> 3;

    unsigned long long acc[4][4];
#pragma unroll
    for (int i = 0; i < 4; i++)
#pragma unroll
        for (int j = 0; j < 4; j++) acc[i][j] = 0ull;

    for (int kt = 0; kt < 2 * HD; kt += 16) {
#pragma unroll
        for (int i = 0; i < 2; i++) {
            int idx = tid + i * 256;
            int mi = idx >> 2, ki = (idx & 3) << 2;
            int m = m0 + mi;
            size_t aoff;
            if (kt < HD) {
                aoff = (size_t)m * HD + kt + ki;
            } else {
                int tt = m >> 6, bb = m & 63;
                aoff = (size_t)TT * BSZ * HD +
                       ((size_t)(TT - 1 - tt) * BSZ + bb) * HD + (kt + ki - HD);
            }
            float4 v = *(const float4*)(g_ys + aoff);
            As[ki + 0][mi] = v.x; As[ki + 1][mi] = v.y;
            As[ki + 2][mi] = v.z; As[ki + 3][mi] = v.w;
        }
        {
            int ni = tid >> 2, ki = (tid & 3) << 2;
            float4 wv = *(const float4*)(Wout + (size_t)(n0 + ni) * (2 * HD) + kt + ki);
            Bs[ki + 0][ni] = wv.x; Bs[ki + 1][ni] = wv.y;
            Bs[ki + 2][ni] = wv.z; Bs[ki + 3][ni] = wv.w;
        }
        __syncthreads();
#pragma unroll
        for (int k = 0; k < 16; k++) {
            float4 a0 = *(const float4*)&As[k][ty * 4];
            ulonglong2 b0 = *(const ulonglong2*)&Bs[k][tx * 8];
            ulonglong2 b1 = *(const ulonglong2*)&Bs[k][tx * 8 + 4];
            float a[4] = {a0.x, a0.y, a0.z, a0.w};
            unsigned long long bb2[4] = {b0.x, b0.y, b1.x, b1.y};
#pragma unroll
            for (int i = 0; i < 4; i++) {
                unsigned long long ad = pk2(a[i], a[i]);
#pragma unroll
                for (int j = 0; j < 4; j++) ffma2(acc[i][j], ad, bb2[j]);
            }
        }
        __syncthreads();
    }

#pragma unroll
    for (int i = 0; i < 4; i++) {
        int m = m0 + ty * 4 + i;
        float* op = out + (size_t)m * HD + n0 + tx * 8;
#pragma unroll
        for (int j = 0; j < 4; j++) {
            float x, y;
            upk2(acc[i][j], x, y);
            int n = n0 + tx * 8 + j * 2;
            float2 o = make_float2(x + bout[n], y + bout[n + 1]);
            *(float2*)(op + j * 2) = o;
        }
    }
}

// =====================================================================
// Kernel D: hidden projection (unchanged)
// =====================================================================
__global__ void __launch_bounds__(256) hid_kernel(
    const float* __restrict__ Whid, const float* __restrict__ bhid,
    float* __restrict__ hid)
{
    const int b = blockIdx.x;
    const int o = threadIdx.x;
    __shared__ float hc[2 * HD];
    for (int k = threadIdx.x; k < 2 * HD; k += 256) {
        hc[k] = (k < HD)
            ? g_ys[((size_t)(TT - 1) * BSZ + b) * HD + k]
            : g_ys[(size_t)TT * BSZ * HD + ((size_t)(TT - 1) * BSZ + b) * HD + (k - HD)];
    }
    __syncthreads();
    float acc = bhid[o];
    const float4* wp = (const float4*)(Whid + (size_t)o * (2 * HD));
    const float4* hp = (const float4*)hc;
#pragma unroll 4
    for (int q = 0; q < (2 * HD) / 4; q++) {
        float4 wv = wp[q], hv = hp[q];
        acc += wv.x * hv.x + wv.y * hv.y + wv.z * hv.z + wv.w * hv.w;
    }
    hid[(size_t)b * HD + o] = tanhf(acc);
}

// =====================================================================
extern "C" void kernel_launch(void* const* d_in, const int* in_sizes, int n_in,
                              void* d_out, int out_size)
{
    const float* src   = (const float*)d_in[0];
    const float* Wih_f = (const float*)d_in[1];
    const float* Whh_f = (const float*)d_in[2];
    const float* bih_f = (const float*)d_in[3];
    const float* bhh_f = (const float*)d_in[4];
    const float* Wih_b = (const float*)d_in[5];
    const float* Whh_b = (const float*)d_in[6];
    const float* bih_b = (const float*)d_in[7];
    const float* bhh_b = (const float*)d_in[8];
    const float* Wout  = (const float*)d_in[9];
    const float* bout  = (const float*)d_in[10];
    const float* Whid  = (const float*)d_in[11];
    const float* bhid  = (const float*)d_in[12];
    float* out = (float*)d_out;

    cudaFuncSetAttribute(gx_mma, cudaFuncAttributeMaxDynamicSharedMemorySize, GX_SMEM_TOTAL);
    cudaFuncSetAttribute(gru_rec, cudaFuncAttributeMaxDynamicSharedMemorySize, GRU_SMEM);

    {
        int n_src = TT * BSZ * IND;
        int n_w   = G3 * IND;
        split_bf16<<<(n_src / 4 + 255) / 256, 256>>>(src, 0, n_src);
        split_bf16<<<(n_w   / 4 + 255) / 256, 256>>>(Wih_f, 1, n_w);
        split_bf16<<<(n_w   / 4 + 255) / 256, 256>>>(Wih_b, 2, n_w);
        whh_pack<<<(2 * G3 * 16 + 255) / 256, 256>>>(Whh_f, Whh_b);
    }

    gx_mma<<<dim3(G3 / 128, TT * BSZ / 128, 2), 512, GX_SMEM_TOTAL>>>(bih_f, bih_b);
    gru_rec<<<32, 384, GRU_SMEM>>>(bhh_f, bhh_b);
    out_gemm<<<dim3(TT * BSZ / 128, HD / 64), 256>>>(Wout, bout, out);
    hid_kernel<<<BSZ, 256>>>(Whid, bhid, out + (size_t)TT * BSZ * HD);
}